// round 6
// baseline (speedup 1.0000x reference)
#include <cuda_runtime.h>
#include <math.h>

#define FULLMASK 0xffffffffu

// ---------------- device scratch (no runtime allocation allowed) -------------
__device__ float g_w3[192 * 192 * 9];   // conv3 weights repacked [i][dy][dx][o]
__device__ float g_convld;              // sum of conv_logdet over the 3 layers

// ============================================================================
// conv_logdet: exact frequency-sum of 2nd-order expansion
//   sum_{u,v} log|det(I+A)| ~= n^2 * [ tr(Kc - I) - 1/2 sum_{s,t} tr(M_st M_{2-s,2-t}) ]
// ============================================================================
__device__ __forceinline__ float cld_partial(const float* __restrict__ K, int c, int n) {
  int tid = threadIdx.x;
  float s = 0.f;
  for (int oi = tid; oi < c * c; oi += 256) {
    int o = oi / c, i = oi - o * c;
    const float* Koi = K + (o * c + i) * 9;
    const float* Kio = K + (i * c + o) * 9;
    bool diag = (o == i);
    if (diag) s += Koi[4] - 1.0f;   // tr(M_center)
    float t2 = 0.f;
#pragma unroll
    for (int st = 0; st < 9; st++) {
      float m1 = Koi[st];
      float m2 = Kio[8 - st];       // (2-s,2-t) pairing
      if (diag && st == 4) { m1 -= 1.0f; m2 -= 1.0f; }
      t2 = fmaf(m1, m2, t2);
    }
    s -= 0.5f * t2;
  }
  return s * (float)(n * n);
}

__global__ void k_logdet(const float* __restrict__ k1, const float* __restrict__ k2,
                         const float* __restrict__ k3) {
  float s = cld_partial(k1, 12, 32) + cld_partial(k2, 48, 16) + cld_partial(k3, 192, 8);
  __shared__ float red[8];
  int lane = threadIdx.x & 31, wid = threadIdx.x >> 5;
#pragma unroll
  for (int off = 16; off > 0; off >>= 1) s += __shfl_down_sync(FULLMASK, s, off);
  if (lane == 0) red[wid] = s;
  __syncthreads();
  if (threadIdx.x == 0) {
    float t = 0.f;
#pragma unroll
    for (int i = 0; i < 8; i++) t += red[i];
    g_convld = t;
  }
}

// repack K3[o][i][dy][dx] -> g_w3[((i*3+dy)*3+dx)*192 + o]
__global__ void k_pack(const float* __restrict__ k3) {
  int idx = blockIdx.x * 256 + threadIdx.x;
  if (idx >= 192 * 192 * 9) return;
  int o = idx / 1728;
  int r = idx - o * 1728;           // i*9 + (dy*3+dx)
  g_w3[r * 192 + o] = k3[idx];
}

// ============================================================================
// data-path helpers
// ============================================================================
__device__ __forceinline__ float lrelu_ld(float v, float& y) {
  float vp = fmaxf(v, 0.f);
  y = fmaf(1.2f, vp, 0.8f * (v - vp));
  float g = vp / (v + 0.001f);
  // reference: yd = 1.2*g; yd = yd + 0.8*(1-yd)  ->  0.8 + 0.24*g
  return __logf(fmaf(0.24f, g, 0.8f));
}

// conv1: 12->12 circular on 32x32.  One warp computes output plane o.
// lane = w; circular w via width-32 shuffle wrap; rolling 3-row window over h.
// Writes lrelu(out) to B in squeeze-2 layout (48,16,16).
__device__ __forceinline__ float conv1_plane(const float* __restrict__ A, float* __restrict__ B,
                                             const float* __restrict__ k1, float bias,
                                             int o, int lane) {
  float acc[32];
#pragma unroll
  for (int h = 0; h < 32; h++) acc[h] = 0.f;
#pragma unroll 1
  for (int i = 0; i < 12; i++) {
    const float* W = k1 + (o * 12 + i) * 9;
    float w0 = __ldg(W + 0), w1 = __ldg(W + 1), w2 = __ldg(W + 2);
    float w3 = __ldg(W + 3), w4 = __ldg(W + 4), w5 = __ldg(W + 5);
    float w6 = __ldg(W + 6), w7 = __ldg(W + 7), w8 = __ldg(W + 8);
    const float* rb = A + i * 1024;
    float am = rb[31 * 32 + lane];
    float a0 = rb[lane];
    float aml = __shfl_sync(FULLMASK, am, (lane + 31) & 31);
    float amr = __shfl_sync(FULLMASK, am, (lane + 1) & 31);
    float a0l = __shfl_sync(FULLMASK, a0, (lane + 31) & 31);
    float a0r = __shfl_sync(FULLMASK, a0, (lane + 1) & 31);
#pragma unroll
    for (int h = 0; h < 32; h++) {
      float ap  = rb[((h + 1) & 31) * 32 + lane];
      float apl = __shfl_sync(FULLMASK, ap, (lane + 31) & 31);
      float apr = __shfl_sync(FULLMASK, ap, (lane + 1) & 31);
      float a = acc[h];
      a = fmaf(w0, aml, a); a = fmaf(w1, am, a); a = fmaf(w2, amr, a);
      a = fmaf(w3, a0l, a); a = fmaf(w4, a0, a); a = fmaf(w5, a0r, a);
      a = fmaf(w6, apl, a); a = fmaf(w7, ap, a); a = fmaf(w8, apr, a);
      acc[h] = a;
      am = a0; aml = a0l; amr = a0r;
      a0 = ap; a0l = apl; a0r = apr;
    }
  }
  float ld = 0.f;
#pragma unroll
  for (int h = 0; h < 32; h++) {
    float y;
    ld += lrelu_ld(acc[h] + bias, y);
    int c2 = o * 4 + ((h & 1) << 1) + (lane & 1);
    B[c2 * 256 + (h >> 1) * 16 + (lane >> 1)] = y;
  }
  return ld;
}

// conv2: 48->48 circular on 16x16.  One warp computes 3 output planes [o0..o0+2].
// lane = (half s, w in 0..15); circular w via width-16 shuffle wrap;
// each thread handles 8 output rows (its half). Writes to A in squeeze-3 layout.
__device__ __forceinline__ float conv2_triple(const float* __restrict__ B, float* __restrict__ A,
                                              const float* __restrict__ k2,
                                              const float* __restrict__ b2,
                                              int o0, int lane) {
  int s  = lane >> 4;
  int w  = lane & 15;
  int hb = s * 8;
  float acc[3][8];
#pragma unroll
  for (int oo = 0; oo < 3; oo++)
#pragma unroll
    for (int r = 0; r < 8; r++) acc[oo][r] = 0.f;
#pragma unroll 1
  for (int i = 0; i < 48; i++) {
    float W[3][9];
#pragma unroll
    for (int oo = 0; oo < 3; oo++) {
      const float* Wp = k2 + ((o0 + oo) * 48 + i) * 9;
#pragma unroll
      for (int t = 0; t < 9; t++) W[oo][t] = __ldg(Wp + t);
    }
    const float* rb = B + i * 256;
    float am = rb[((hb + 15) & 15) * 16 + w];
    float a0 = rb[hb * 16 + w];
    float aml = __shfl_sync(FULLMASK, am, (w + 15) & 15, 16);
    float amr = __shfl_sync(FULLMASK, am, (w + 1) & 15, 16);
    float a0l = __shfl_sync(FULLMASK, a0, (w + 15) & 15, 16);
    float a0r = __shfl_sync(FULLMASK, a0, (w + 1) & 15, 16);
#pragma unroll
    for (int r = 0; r < 8; r++) {
      float ap  = rb[((hb + r + 1) & 15) * 16 + w];
      float apl = __shfl_sync(FULLMASK, ap, (w + 15) & 15, 16);
      float apr = __shfl_sync(FULLMASK, ap, (w + 1) & 15, 16);
#pragma unroll
      for (int oo = 0; oo < 3; oo++) {
        float a = acc[oo][r];
        a = fmaf(W[oo][0], aml, a); a = fmaf(W[oo][1], am, a); a = fmaf(W[oo][2], amr, a);
        a = fmaf(W[oo][3], a0l, a); a = fmaf(W[oo][4], a0, a); a = fmaf(W[oo][5], a0r, a);
        a = fmaf(W[oo][6], apl, a); a = fmaf(W[oo][7], ap, a); a = fmaf(W[oo][8], apr, a);
        acc[oo][r] = a;
      }
      am = a0; aml = a0l; amr = a0r;
      a0 = ap; a0l = apl; a0r = apr;
    }
  }
  float ld = 0.f;
#pragma unroll
  for (int oo = 0; oo < 3; oo++) {
    int o = o0 + oo;
    float bias = __ldg(b2 + o);
#pragma unroll
    for (int r = 0; r < 8; r++) {
      int h = hb + r;
      float y;
      ld += lrelu_ld(acc[oo][r] + bias, y);
      int c3 = o * 4 + ((h & 1) << 1) + (w & 1);
      A[c3 * 64 + (h >> 1) * 8 + (w >> 1)] = y;
    }
  }
  return ld;
}

// ============================================================================
// fused per-sample pipeline: one CTA per batch sample
// ============================================================================
__global__ void __launch_bounds__(256, 2) k_main(
    const float* __restrict__ x,
    const float* __restrict__ k1, const float* __restrict__ b1,
    const float* __restrict__ k2, const float* __restrict__ b2,
    const float* __restrict__ b3,
    float* __restrict__ out)
{
  extern __shared__ float smem[];
  float* bufA = smem;                // 12288 floats
  float* bufB = smem + 12288;        // 12288 floats
  __shared__ float red[8];

  int b = blockIdx.x;
  int tid = threadIdx.x;
  int wid = tid >> 5, lane = tid & 31;
  const float* xb = x + (size_t)b * 12288;
  float ldsum = 0.f;

  // ---- stage 0: logit + squeeze -> bufA (12,32,32) ----
#pragma unroll 4
  for (int k = 0; k < 48; k++) {
    int idx = tid + k * 256;
    float v  = xb[idx];
    float xs = fmaf(v, 0.999f, 0.0005f);
    float la = __logf(xs);
    float lb = __logf(1.0f - xs);
    ldsum -= (la + lb);
    int c = idx >> 12;
    int rem = idx & 4095;
    int h = rem >> 6, w = rem & 63;
    bufA[(c * 4 + ((h & 1) << 1) + (w & 1)) * 1024 + (h >> 1) * 32 + (w >> 1)] = la - lb;
  }
  __syncthreads();

  // ---- conv1 + lrelu + squeeze -> bufB (48,16,16) ----
  ldsum += conv1_plane(bufA, bufB, k1, __ldg(b1 + wid), wid, lane);
  if (wid < 4)
    ldsum += conv1_plane(bufA, bufB, k1, __ldg(b1 + 8 + wid), 8 + wid, lane);
  __syncthreads();

  // ---- conv2 + lrelu + squeeze -> bufA (192,8,8) ----
  ldsum += conv2_triple(bufB, bufA, k2, b2, wid * 6,     lane);
  ldsum += conv2_triple(bufB, bufA, k2, b2, wid * 6 + 3, lane);
  __syncthreads();

  // ---- conv3 -> out; thread = (o-group of 6, h); 6x8 register tile ----
  {
    int og = tid >> 3;               // 0..31
    int h  = tid & 7;
    int hm = (h + 7) & 7, hp = (h + 1) & 7;
    float acc[6][8];
#pragma unroll
    for (int oo = 0; oo < 6; oo++)
#pragma unroll
      for (int ww = 0; ww < 8; ww++) acc[oo][ww] = 0.f;

    const float* wb0 = g_w3 + og * 6;
#pragma unroll 1
    for (int i = 0; i < 192; i++) {
      const float* rb = bufA + i * 64;
      float rm[8], r0[8], rp[8];
      {
        float4 t0 = *(const float4*)(rb + hm * 8);
        float4 t1 = *(const float4*)(rb + hm * 8 + 4);
        rm[0]=t0.x; rm[1]=t0.y; rm[2]=t0.z; rm[3]=t0.w; rm[4]=t1.x; rm[5]=t1.y; rm[6]=t1.z; rm[7]=t1.w;
        t0 = *(const float4*)(rb + h * 8);
        t1 = *(const float4*)(rb + h * 8 + 4);
        r0[0]=t0.x; r0[1]=t0.y; r0[2]=t0.z; r0[3]=t0.w; r0[4]=t1.x; r0[5]=t1.y; r0[6]=t1.z; r0[7]=t1.w;
        t0 = *(const float4*)(rb + hp * 8);
        t1 = *(const float4*)(rb + hp * 8 + 4);
        rp[0]=t0.x; rp[1]=t0.y; rp[2]=t0.z; rp[3]=t0.w; rp[4]=t1.x; rp[5]=t1.y; rp[6]=t1.z; rp[7]=t1.w;
      }
      const float* wbi = wb0 + i * 1728;
#pragma unroll
      for (int dy = 0; dy < 3; dy++) {
#pragma unroll
        for (int dx = 0; dx < 3; dx++) {
          const float* wp = wbi + (dy * 3 + dx) * 192;
          float2 wa  = __ldg((const float2*)(wp));
          float2 wbv = __ldg((const float2*)(wp + 2));
          float2 wc  = __ldg((const float2*)(wp + 4));
          float ws[6] = {wa.x, wa.y, wbv.x, wbv.y, wc.x, wc.y};
#pragma unroll
          for (int oo = 0; oo < 6; oo++) {
            float wv = ws[oo];
            if (dy == 0) {
#pragma unroll
              for (int ww = 0; ww < 8; ww++)
                acc[oo][ww] = fmaf(wv, rm[(ww + dx + 7) & 7], acc[oo][ww]);
            } else if (dy == 1) {
#pragma unroll
              for (int ww = 0; ww < 8; ww++)
                acc[oo][ww] = fmaf(wv, r0[(ww + dx + 7) & 7], acc[oo][ww]);
            } else {
#pragma unroll
              for (int ww = 0; ww < 8; ww++)
                acc[oo][ww] = fmaf(wv, rp[(ww + dx + 7) & 7], acc[oo][ww]);
            }
          }
        }
      }
    }

    float* yo = out + (size_t)b * 12288 + h * 8;
#pragma unroll
    for (int oo = 0; oo < 6; oo++) {
      int o = og * 6 + oo;
      float bias = __ldg(b3 + o);
      float y0 = acc[oo][0] + bias, y1 = acc[oo][1] + bias;
      float y2 = acc[oo][2] + bias, y3 = acc[oo][3] + bias;
      float y4 = acc[oo][4] + bias, y5 = acc[oo][5] + bias;
      float y6 = acc[oo][6] + bias, y7 = acc[oo][7] + bias;
      ldsum -= 0.5f * (y0*y0 + y1*y1 + y2*y2 + y3*y3 + y4*y4 + y5*y5 + y6*y6 + y7*y7);
      *(float4*)(yo + o * 64)     = make_float4(y0, y1, y2, y3);
      *(float4*)(yo + o * 64 + 4) = make_float4(y4, y5, y6, y7);
    }
  }

  // ---- per-sample log_pdf reduction ----
#pragma unroll
  for (int off = 16; off > 0; off >>= 1) ldsum += __shfl_down_sync(FULLMASK, ldsum, off);
  if (lane == 0) red[wid] = ldsum;
  __syncthreads();
  if (tid == 0) {
    float t = 0.f;
#pragma unroll
    for (int i = 0; i < 8; i++) t += red[i];
    out[512 * 12288 + b] = t - 0.5f * 1.8378770664093453f * 12288.0f + g_convld;
  }
}

// ============================================================================
extern "C" void kernel_launch(void* const* d_in, const int* in_sizes, int n_in,
                              void* d_out, int out_size) {
  // map inputs by element count (all sizes are distinct) — robust to ordering
  const float *x = 0, *k1 = 0, *b1 = 0, *k2 = 0, *b2 = 0, *k3 = 0, *b3 = 0;
  for (int i = 0; i < n_in; i++) {
    const float* p = (const float*)d_in[i];
    switch (in_sizes[i]) {
      case 512 * 12288:   x  = p; break;
      case 12 * 12 * 9:   k1 = p; break;
      case 12:            b1 = p; break;
      case 48 * 48 * 9:   k2 = p; break;
      case 48:            b2 = p; break;
      case 192 * 192 * 9: k3 = p; break;
      case 192:           b3 = p; break;
    }
  }
  float* out = (float*)d_out;

  cudaFuncSetAttribute(k_main, cudaFuncAttributeMaxDynamicSharedMemorySize, 98304);

  k_logdet<<<1, 256>>>(k1, k2, k3);
  k_pack<<<(192 * 192 * 9 + 255) / 256, 256>>>(k3);
  k_main<<<512, 256, 98304>>>(x, k1, b1, k2, b2, b3, out);
}

// round 10
// speedup vs baseline: 1.0317x; 1.0317x over previous
#include <cuda_runtime.h>
#include <math.h>

#define FULLMASK 0xffffffffu
typedef unsigned long long ull;

// ---------------- device scratch (no runtime allocation allowed) -------------
__device__ ull g_w3d[192 * 192 * 9];    // conv3 weights, duplicated pairs {w,w}, [i][tap][o]
__device__ ull g_w2d[48 * 48 * 9];      // conv2 weights, duplicated pairs {w,w}, [i][tap][o]
__device__ float g_convld;              // sum of conv_logdet over the 3 layers

// ---------------- f32x2 helpers ----------------------------------------------
__device__ __forceinline__ ull ffma2(ull a, ull b, ull c) {
  ull d;
  asm("fma.rn.f32x2 %0, %1, %2, %3;" : "=l"(d) : "l"(a), "l"(b), "l"(c));
  return d;
}
__device__ __forceinline__ ull pack2(float lo, float hi) {
  ull r;
  asm("mov.b64 %0, {%1, %2};" : "=l"(r) : "f"(lo), "f"(hi));
  return r;
}
__device__ __forceinline__ float2 unpack2(ull v) {
  float2 r;
  asm("mov.b64 {%0, %1}, %2;" : "=f"(r.x), "=f"(r.y) : "l"(v));
  return r;
}

// ============================================================================
// conv_logdet: exact frequency-sum of the 2nd-order log det expansion
//   sum_{u,v} log|det(I+A)| ~= n^2 * [ tr(Kc - I) - 1/2 sum_{s,t} tr(M_st M_{2-s,2-t}) ]
// parallelized across the grid, accumulated with atomics.
// ============================================================================
__device__ __forceinline__ float cld_partial_strided(const float* __restrict__ K,
                                                     int c, int n, int base, int stride) {
  float s = 0.f;
  for (int oi = base; oi < c * c; oi += stride) {
    int o = oi / c, i = oi - o * c;
    const float* Koi = K + (o * c + i) * 9;
    const float* Kio = K + (i * c + o) * 9;
    bool diag = (o == i);
    if (diag) s += Koi[4] - 1.0f;
    float t2 = 0.f;
#pragma unroll
    for (int st = 0; st < 9; st++) {
      float m1 = __ldg(Koi + st);
      float m2 = __ldg(Kio + 8 - st);
      if (diag && st == 4) { m1 -= 1.0f; m2 -= 1.0f; }
      t2 = fmaf(m1, m2, t2);
    }
    s -= 0.5f * t2;
  }
  return s * (float)(n * n);
}

__global__ void k_logdet(const float* __restrict__ k1, const float* __restrict__ k2,
                         const float* __restrict__ k3) {
  int base = blockIdx.x * 256 + threadIdx.x;
  int stride = gridDim.x * 256;
  float s = cld_partial_strided(k3, 192, 8, base, stride)
          + cld_partial_strided(k2, 48, 16, base, stride)
          + cld_partial_strided(k1, 12, 32, base, stride);
  __shared__ float red[8];
  int lane = threadIdx.x & 31, wid = threadIdx.x >> 5;
#pragma unroll
  for (int off = 16; off > 0; off >>= 1) s += __shfl_down_sync(FULLMASK, s, off);
  if (lane == 0) red[wid] = s;
  __syncthreads();
  if (threadIdx.x == 0) {
    float t = 0.f;
#pragma unroll
    for (int i = 0; i < 8; i++) t += red[i];
    atomicAdd(&g_convld, t);
  }
}

// pack duplicated weight pairs; also zero g_convld (runs before k_logdet)
__global__ void k_pack(const float* __restrict__ k2, const float* __restrict__ k3) {
  int idx = blockIdx.x * 256 + threadIdx.x;
  if (idx == 0) g_convld = 0.f;
  if (idx < 192 * 192 * 9) {
    int o = idx / 1728;
    int r = idx - o * 1728;              // i*9 + tap
    ull bits = (ull)__float_as_uint(k3[idx]);
    g_w3d[r * 192 + o] = (bits << 32) | bits;
  }
  if (idx < 48 * 48 * 9) {
    int o = idx / 432;
    int r = idx - o * 432;
    ull bits = (ull)__float_as_uint(k2[idx]);
    g_w2d[r * 48 + o] = (bits << 32) | bits;
  }
}

// ============================================================================
// data-path helpers
// ============================================================================
__device__ __forceinline__ float lrelu_ld(float v, float& y) {
  float vp = fmaxf(v, 0.f);
  y = fmaf(1.2f, vp, 0.8f * (v - vp));
  float g = vp / (v + 0.001f);
  // reference: yd = 1.2*g; yd = yd + 0.8*(1-yd)  ->  0.8 + 0.24*g
  return __logf(fmaf(0.24f, g, 0.8f));
}

#define PS2 272   // bufB plane stride: 16 rows * 17 floats (pitch 17 kills bank conflicts)

// conv1: 12->12 circular on 32x32.  One warp per output plane; lane = w,
// circular w via width-32 shuffles, rolling 3-row window. Writes lrelu(out)
// into bufB with squeeze-2 layout (48 planes, pitch-17 rows).
__device__ __forceinline__ float conv1_plane(const float* __restrict__ A, float* __restrict__ B,
                                             const float* __restrict__ k1, float bias,
                                             int o, int lane) {
  float acc[32];
#pragma unroll
  for (int h = 0; h < 32; h++) acc[h] = 0.f;
#pragma unroll 1
  for (int i = 0; i < 12; i++) {
    const float* W = k1 + (o * 12 + i) * 9;
    float w0 = __ldg(W + 0), w1 = __ldg(W + 1), w2 = __ldg(W + 2);
    float w3 = __ldg(W + 3), w4 = __ldg(W + 4), w5 = __ldg(W + 5);
    float w6 = __ldg(W + 6), w7 = __ldg(W + 7), w8 = __ldg(W + 8);
    const float* rb = A + i * 1024;
    float am = rb[31 * 32 + lane];
    float a0 = rb[lane];
    float aml = __shfl_sync(FULLMASK, am, (lane + 31) & 31);
    float amr = __shfl_sync(FULLMASK, am, (lane + 1) & 31);
    float a0l = __shfl_sync(FULLMASK, a0, (lane + 31) & 31);
    float a0r = __shfl_sync(FULLMASK, a0, (lane + 1) & 31);
#pragma unroll
    for (int h = 0; h < 32; h++) {
      float ap  = rb[((h + 1) & 31) * 32 + lane];
      float apl = __shfl_sync(FULLMASK, ap, (lane + 31) & 31);
      float apr = __shfl_sync(FULLMASK, ap, (lane + 1) & 31);
      float a = acc[h];
      a = fmaf(w0, aml, a); a = fmaf(w1, am, a); a = fmaf(w2, amr, a);
      a = fmaf(w3, a0l, a); a = fmaf(w4, a0, a); a = fmaf(w5, a0r, a);
      a = fmaf(w6, apl, a); a = fmaf(w7, ap, a); a = fmaf(w8, apr, a);
      acc[h] = a;
      am = a0; aml = a0l; amr = a0r;
      a0 = ap; a0l = apl; a0r = apr;
    }
  }
  float ld = 0.f;
#pragma unroll
  for (int h = 0; h < 32; h++) {
    float y;
    ld += lrelu_ld(acc[h] + bias, y);
    int c2 = o * 4 + ((h & 1) << 1) + (lane & 1);
    B[c2 * PS2 + (h >> 1) * 17 + (lane >> 1)] = y;
  }
  return ld;
}

// conv2: 48->48 circular on 16x16, FFMA2 over w-pairs.
// thread = (og = tid>>4 -> outs og*3..og*3+2, h = tid&15). Rows register-
// resident; pitch-17 scalar LDS is conflict-free (17h mod 32 distinct).
__device__ __forceinline__ float conv2_ffma2(const float* __restrict__ B, float* __restrict__ A,
                                             const float* __restrict__ b2, int tid) {
  int og = tid >> 4, h = tid & 15;
  int o0 = og * 3;
  ull acc[3][8];
#pragma unroll
  for (int oo = 0; oo < 3; oo++)
#pragma unroll
    for (int j = 0; j < 8; j++) acc[oo][j] = 0ull;

#pragma unroll 1
  for (int i = 0; i < 48; i++) {
    const float* rb = B + i * PS2;
    const ull* __restrict__ wb = g_w2d + i * 9 * 48 + o0;
#pragma unroll
    for (int dy = 0; dy < 3; dy++) {
      int hr = ((h + dy + 15) & 15) * 17;
      float r[16];
#pragma unroll
      for (int w = 0; w < 16; w++) r[w] = rb[hr + w];
      ull Aa[8], Oo[8];
#pragma unroll
      for (int j = 0; j < 8; j++) {
        Aa[j] = pack2(r[2 * j], r[2 * j + 1]);
        Oo[j] = pack2(r[2 * j + 1], r[(2 * j + 2) & 15]);
      }
      const ull* __restrict__ wt = wb + dy * 3 * 48;
#pragma unroll
      for (int dx = 0; dx < 3; dx++) {
        const ull* __restrict__ wp = wt + dx * 48;
        ull w0 = wp[0], w1 = wp[1], w2 = wp[2];
#pragma unroll
        for (int j = 0; j < 8; j++) {
          ull op = (dx == 1) ? Aa[j] : (dx == 2) ? Oo[j] : Oo[(j + 7) & 7];
          acc[0][j] = ffma2(w0, op, acc[0][j]);
          acc[1][j] = ffma2(w1, op, acc[1][j]);
          acc[2][j] = ffma2(w2, op, acc[2][j]);
        }
      }
    }
  }

  float ld = 0.f;
#pragma unroll
  for (int oo = 0; oo < 3; oo++) {
    int o = o0 + oo;
    float bias = __ldg(b2 + o);
#pragma unroll
    for (int j = 0; j < 8; j++) {
      float2 p = unpack2(acc[oo][j]);
      float y0, y1;
      ld += lrelu_ld(p.x + bias, y0);
      ld += lrelu_ld(p.y + bias, y1);
      int base = (h >> 1) * 8 + j;       // w>>1 = j for both halves
      int c3e = o * 4 + ((h & 1) << 1);  // w even
      A[c3e * 64 + base] = y0;
      A[(c3e + 1) * 64 + base] = y1;     // w odd
    }
  }
  return ld;
}

// ============================================================================
// fused per-sample pipeline: one CTA per batch sample
// ============================================================================
__global__ void __launch_bounds__(256, 2) k_main(
    const float* __restrict__ x,
    const float* __restrict__ k1, const float* __restrict__ b1,
    const float* __restrict__ b2,
    const float* __restrict__ b3,
    float* __restrict__ out)
{
  extern __shared__ float smem[];
  float* bufA = smem;                 // 12288 floats (conv1 in / conv3 in)
  float* bufB = smem + 12288;         // 13056 floats (48 x 16 x pitch17)
  __shared__ float red[8];

  int b = blockIdx.x;
  int tid = threadIdx.x;
  int wid = tid >> 5, lane = tid & 31;
  const float* xb = x + (size_t)b * 12288;
  float ldsum = 0.f;

  // ---- stage 0: logit + squeeze -> bufA (12,32,32) ----
#pragma unroll 4
  for (int k = 0; k < 48; k++) {
    int idx = tid + k * 256;
    float v  = xb[idx];
    float xs = fmaf(v, 0.999f, 0.0005f);
    float la = __logf(xs);
    float lb = __logf(1.0f - xs);
    ldsum -= (la + lb);
    int c = idx >> 12;
    int rem = idx & 4095;
    int h = rem >> 6, w = rem & 63;
    bufA[(c * 4 + ((h & 1) << 1) + (w & 1)) * 1024 + (h >> 1) * 32 + (w >> 1)] = la - lb;
  }
  __syncthreads();

  // ---- conv1 + lrelu + squeeze -> bufB ----
  ldsum += conv1_plane(bufA, bufB, k1, __ldg(b1 + wid), wid, lane);
  if (wid < 4)
    ldsum += conv1_plane(bufA, bufB, k1, __ldg(b1 + 8 + wid), 8 + wid, lane);
  __syncthreads();

  // ---- conv2 (FFMA2) + lrelu + squeeze -> bufA (192,8,8) ----
  ldsum += conv2_ffma2(bufB, bufA, b2, tid);
  __syncthreads();

  // ---- conv3 (FFMA2) -> out; thread = (og of 6 outs, h); 6x(4 pair) tile ----
  {
    int og = tid >> 3;                 // 0..31
    int h  = tid & 7;
    ull acc[6][4];
#pragma unroll
    for (int oo = 0; oo < 6; oo++)
#pragma unroll
      for (int j = 0; j < 4; j++) acc[oo][j] = 0ull;

#pragma unroll 1
    for (int i = 0; i < 192; i++) {
      const float* rb = bufA + i * 64;
#pragma unroll
      for (int dy = 0; dy < 3; dy++) {
        int hr = ((h + dy + 7) & 7) * 8;
        float4 t0 = *(const float4*)(rb + hr);
        float4 t1 = *(const float4*)(rb + hr + 4);
        float r[8] = {t0.x, t0.y, t0.z, t0.w, t1.x, t1.y, t1.z, t1.w};
        ull Aa[4], Oo[4];
#pragma unroll
        for (int j = 0; j < 4; j++) {
          Aa[j] = pack2(r[2 * j], r[2 * j + 1]);
          Oo[j] = pack2(r[2 * j + 1], r[(2 * j + 2) & 7]);
        }
#pragma unroll
        for (int dx = 0; dx < 3; dx++) {
          // duplicated weight pairs: 3 x 128-bit loads give 6 outs
          const ulonglong2* __restrict__ wp =
              (const ulonglong2*)g_w3d + ((i * 9 + dy * 3 + dx) * 96 + og * 3);
          ulonglong2 wa = wp[0], wbv = wp[1], wc = wp[2];
          ull w[6] = {wa.x, wa.y, wbv.x, wbv.y, wc.x, wc.y};
#pragma unroll
          for (int j = 0; j < 4; j++) {
            ull op = (dx == 1) ? Aa[j] : (dx == 2) ? Oo[j] : Oo[(j + 3) & 3];
#pragma unroll
            for (int oo = 0; oo < 6; oo++)
              acc[oo][j] = ffma2(w[oo], op, acc[oo][j]);
          }
        }
      }
    }

    float* yo = out + (size_t)b * 12288 + h * 8;
#pragma unroll
    for (int oo = 0; oo < 6; oo++) {
      int o = og * 6 + oo;
      float bias = __ldg(b3 + o);
      float2 p0 = unpack2(acc[oo][0]);
      float2 p1 = unpack2(acc[oo][1]);
      float2 p2 = unpack2(acc[oo][2]);
      float2 p3 = unpack2(acc[oo][3]);
      float y0 = p0.x + bias, y1 = p0.y + bias;
      float y2 = p1.x + bias, y3 = p1.y + bias;
      float y4 = p2.x + bias, y5 = p2.y + bias;
      float y6 = p3.x + bias, y7 = p3.y + bias;
      ldsum -= 0.5f * (y0*y0 + y1*y1 + y2*y2 + y3*y3 + y4*y4 + y5*y5 + y6*y6 + y7*y7);
      *(float4*)(yo + o * 64)     = make_float4(y0, y1, y2, y3);
      *(float4*)(yo + o * 64 + 4) = make_float4(y4, y5, y6, y7);
    }
  }

  // ---- per-sample log_pdf reduction ----
#pragma unroll
  for (int off = 16; off > 0; off >>= 1) ldsum += __shfl_down_sync(FULLMASK, ldsum, off);
  if (lane == 0) red[wid] = ldsum;
  __syncthreads();
  if (tid == 0) {
    float t = 0.f;
#pragma unroll
    for (int i = 0; i < 8; i++) t += red[i];
    out[512 * 12288 + b] = t - 0.5f * 1.8378770664093453f * 12288.0f + g_convld;
  }
}

// ============================================================================
extern "C" void kernel_launch(void* const* d_in, const int* in_sizes, int n_in,
                              void* d_out, int out_size) {
  // map inputs by element count (all sizes distinct) — robust to ordering
  const float *x = 0, *k1 = 0, *b1 = 0, *k2 = 0, *b2 = 0, *k3 = 0, *b3 = 0;
  for (int i = 0; i < n_in; i++) {
    const float* p = (const float*)d_in[i];
    switch (in_sizes[i]) {
      case 512 * 12288:   x  = p; break;
      case 12 * 12 * 9:   k1 = p; break;
      case 12:            b1 = p; break;
      case 48 * 48 * 9:   k2 = p; break;
      case 48:            b2 = p; break;
      case 192 * 192 * 9: k3 = p; break;
      case 192:           b3 = p; break;
    }
  }
  float* out = (float*)d_out;

  const int SMEM_BYTES = (12288 + 13056) * 4;   // 101376
  cudaFuncSetAttribute(k_main, cudaFuncAttributeMaxDynamicSharedMemorySize, SMEM_BYTES);

  k_pack<<<(192 * 192 * 9 + 255) / 256, 256>>>(k2, k3);   // also zeroes g_convld
  k_logdet<<<160, 256>>>(k1, k2, k3);
  k_main<<<512, 256, SMEM_BYTES>>>(x, k1, b1, b2, b3, out);
}

// round 11
// speedup vs baseline: 1.2475x; 1.2092x over previous
#include <cuda_runtime.h>
#include <math.h>

#define FULLMASK 0xffffffffu

// ---------------- device scratch (no runtime allocation allowed) -------------
__device__ float g_w3p[192 * 192 * 9];  // conv3 weights repacked [i][tap][o]
__device__ float g_convld;              // sum of conv_logdet over the 3 layers

// ============================================================================
// conv_logdet: exact frequency-sum of the 2nd-order log det expansion
//   sum_{u,v} log|det(I+A)| ~= n^2 * [ tr(Kc - I) - 1/2 sum_{s,t} tr(M_st M_{2-s,2-t}) ]
// parallelized across the grid, accumulated with atomics.
// ============================================================================
__device__ __forceinline__ float cld_partial_strided(const float* __restrict__ K,
                                                     int c, int n, int base, int stride) {
  float s = 0.f;
  for (int oi = base; oi < c * c; oi += stride) {
    int o = oi / c, i = oi - o * c;
    const float* Koi = K + (o * c + i) * 9;
    const float* Kio = K + (i * c + o) * 9;
    bool diag = (o == i);
    if (diag) s += Koi[4] - 1.0f;
    float t2 = 0.f;
#pragma unroll
    for (int st = 0; st < 9; st++) {
      float m1 = __ldg(Koi + st);
      float m2 = __ldg(Kio + 8 - st);
      if (diag && st == 4) { m1 -= 1.0f; m2 -= 1.0f; }
      t2 = fmaf(m1, m2, t2);
    }
    s -= 0.5f * t2;
  }
  return s * (float)(n * n);
}

__global__ void k_logdet(const float* __restrict__ k1, const float* __restrict__ k2,
                         const float* __restrict__ k3) {
  int base = blockIdx.x * 256 + threadIdx.x;
  int stride = gridDim.x * 256;
  float s = cld_partial_strided(k3, 192, 8, base, stride)
          + cld_partial_strided(k2, 48, 16, base, stride)
          + cld_partial_strided(k1, 12, 32, base, stride);
  __shared__ float red[8];
  int lane = threadIdx.x & 31, wid = threadIdx.x >> 5;
#pragma unroll
  for (int off = 16; off > 0; off >>= 1) s += __shfl_down_sync(FULLMASK, s, off);
  if (lane == 0) red[wid] = s;
  __syncthreads();
  if (threadIdx.x == 0) {
    float t = 0.f;
#pragma unroll
    for (int i = 0; i < 8; i++) t += red[i];
    atomicAdd(&g_convld, t);
  }
}

// repack K3[o][i][dy][dx] -> g_w3p[((i*3+dy)*3+dx)*192 + o]; also zero g_convld
__global__ void k_pack(const float* __restrict__ k3) {
  int idx = blockIdx.x * 256 + threadIdx.x;
  if (idx == 0) g_convld = 0.f;
  if (idx >= 192 * 192 * 9) return;
  int o = idx / 1728;
  int r = idx - o * 1728;              // i*9 + tap
  g_w3p[r * 192 + o] = k3[idx];
}

// ============================================================================
// data-path helpers
// ============================================================================
__device__ __forceinline__ float lrelu_ld(float v, float& y) {
  float vp = fmaxf(v, 0.f);
  y = fmaf(1.2f, vp, 0.8f * (v - vp));
  float g = vp / (v + 0.001f);
  // reference: yd = 1.2*g; yd = yd + 0.8*(1-yd)  ->  0.8 + 0.24*g
  return __logf(fmaf(0.24f, g, 0.8f));
}

// conv1: 12->12 circular on 32x32.  One warp per output plane; lane = w,
// circular w via width-32 shuffles, rolling 3-row window. Writes lrelu(out)
// into bufB with squeeze-2 layout (48,16,16).
__device__ __forceinline__ float conv1_plane(const float* __restrict__ A, float* __restrict__ B,
                                             const float* __restrict__ k1, float bias,
                                             int o, int lane) {
  float acc[32];
#pragma unroll
  for (int h = 0; h < 32; h++) acc[h] = 0.f;
#pragma unroll 1
  for (int i = 0; i < 12; i++) {
    const float* W = k1 + (o * 12 + i) * 9;
    float w0 = __ldg(W + 0), w1 = __ldg(W + 1), w2 = __ldg(W + 2);
    float w3 = __ldg(W + 3), w4 = __ldg(W + 4), w5 = __ldg(W + 5);
    float w6 = __ldg(W + 6), w7 = __ldg(W + 7), w8 = __ldg(W + 8);
    const float* rb = A + i * 1024;
    float am = rb[31 * 32 + lane];
    float a0 = rb[lane];
    float aml = __shfl_sync(FULLMASK, am, (lane + 31) & 31);
    float amr = __shfl_sync(FULLMASK, am, (lane + 1) & 31);
    float a0l = __shfl_sync(FULLMASK, a0, (lane + 31) & 31);
    float a0r = __shfl_sync(FULLMASK, a0, (lane + 1) & 31);
#pragma unroll
    for (int h = 0; h < 32; h++) {
      float ap  = rb[((h + 1) & 31) * 32 + lane];
      float apl = __shfl_sync(FULLMASK, ap, (lane + 31) & 31);
      float apr = __shfl_sync(FULLMASK, ap, (lane + 1) & 31);
      float a = acc[h];
      a = fmaf(w0, aml, a); a = fmaf(w1, am, a); a = fmaf(w2, amr, a);
      a = fmaf(w3, a0l, a); a = fmaf(w4, a0, a); a = fmaf(w5, a0r, a);
      a = fmaf(w6, apl, a); a = fmaf(w7, ap, a); a = fmaf(w8, apr, a);
      acc[h] = a;
      am = a0; aml = a0l; amr = a0r;
      a0 = ap; a0l = apl; a0r = apr;
    }
  }
  float ld = 0.f;
#pragma unroll
  for (int h = 0; h < 32; h++) {
    float y;
    ld += lrelu_ld(acc[h] + bias, y);
    int c2 = o * 4 + ((h & 1) << 1) + (lane & 1);
    B[c2 * 256 + (h >> 1) * 16 + (lane >> 1)] = y;
  }
  return ld;
}

// conv2: 48->48 circular on 16x16.  One warp computes 3 output planes [o0..o0+2].
// lane = (half s, w in 0..15); circular w via width-16 shuffle wrap;
// each thread handles 8 output rows (its half). Writes to A in squeeze-3 layout.
// Weights (83KB total) are L1-resident after the first pass.
__device__ __forceinline__ float conv2_triple(const float* __restrict__ B, float* __restrict__ A,
                                              const float* __restrict__ k2,
                                              const float* __restrict__ b2,
                                              int o0, int lane) {
  int s  = lane >> 4;
  int w  = lane & 15;
  int hb = s * 8;
  float acc[3][8];
#pragma unroll
  for (int oo = 0; oo < 3; oo++)
#pragma unroll
    for (int r = 0; r < 8; r++) acc[oo][r] = 0.f;
#pragma unroll 1
  for (int i = 0; i < 48; i++) {
    float W[3][9];
#pragma unroll
    for (int oo = 0; oo < 3; oo++) {
      const float* Wp = k2 + ((o0 + oo) * 48 + i) * 9;
#pragma unroll
      for (int t = 0; t < 9; t++) W[oo][t] = __ldg(Wp + t);
    }
    const float* rb = B + i * 256;
    float am = rb[((hb + 15) & 15) * 16 + w];
    float a0 = rb[hb * 16 + w];
    float aml = __shfl_sync(FULLMASK, am, (w + 15) & 15, 16);
    float amr = __shfl_sync(FULLMASK, am, (w + 1) & 15, 16);
    float a0l = __shfl_sync(FULLMASK, a0, (w + 15) & 15, 16);
    float a0r = __shfl_sync(FULLMASK, a0, (w + 1) & 15, 16);
#pragma unroll
    for (int r = 0; r < 8; r++) {
      float ap  = rb[((hb + r + 1) & 15) * 16 + w];
      float apl = __shfl_sync(FULLMASK, ap, (w + 15) & 15, 16);
      float apr = __shfl_sync(FULLMASK, ap, (w + 1) & 15, 16);
#pragma unroll
      for (int oo = 0; oo < 3; oo++) {
        float a = acc[oo][r];
        a = fmaf(W[oo][0], aml, a); a = fmaf(W[oo][1], am, a); a = fmaf(W[oo][2], amr, a);
        a = fmaf(W[oo][3], a0l, a); a = fmaf(W[oo][4], a0, a); a = fmaf(W[oo][5], a0r, a);
        a = fmaf(W[oo][6], apl, a); a = fmaf(W[oo][7], ap, a); a = fmaf(W[oo][8], apr, a);
        acc[oo][r] = a;
      }
      am = a0; aml = a0l; amr = a0r;
      a0 = ap; a0l = apl; a0r = apr;
    }
  }
  float ld = 0.f;
#pragma unroll
  for (int oo = 0; oo < 3; oo++) {
    int o = o0 + oo;
    float bias = __ldg(b2 + o);
#pragma unroll
    for (int r = 0; r < 8; r++) {
      int h = hb + r;
      float y;
      ld += lrelu_ld(acc[oo][r] + bias, y);
      int c3 = o * 4 + ((h & 1) << 1) + (w & 1);
      A[c3 * 64 + (h >> 1) * 8 + (w >> 1)] = y;
    }
  }
  return ld;
}

// ============================================================================
// fused per-sample pipeline: one CTA per batch sample
// ============================================================================
#define CH 6   // conv3 input channels per SMEM weight chunk (6*1728 floats = 41.5KB)

__global__ void __launch_bounds__(256, 2) k_main(
    const float* __restrict__ x,
    const float* __restrict__ k1, const float* __restrict__ b1,
    const float* __restrict__ k2, const float* __restrict__ b2,
    const float* __restrict__ b3,
    float* __restrict__ out)
{
  extern __shared__ float smem[];
  float* bufA = smem;                 // 12288 floats (conv1 in / conv3 in)
  float* bufB = smem + 12288;         // 12288 floats (conv2 in; conv3 weight stage)
  __shared__ float red[8];

  int b = blockIdx.x;
  int tid = threadIdx.x;
  int wid = tid >> 5, lane = tid & 31;
  const float* xb = x + (size_t)b * 12288;
  float ldsum = 0.f;

  // ---- stage 0: logit + squeeze -> bufA (12,32,32) ----
#pragma unroll 4
  for (int k = 0; k < 48; k++) {
    int idx = tid + k * 256;
    float v  = xb[idx];
    float xs = fmaf(v, 0.999f, 0.0005f);
    float la = __logf(xs);
    float lb = __logf(1.0f - xs);
    ldsum -= (la + lb);
    int c = idx >> 12;
    int rem = idx & 4095;
    int h = rem >> 6, w = rem & 63;
    bufA[(c * 4 + ((h & 1) << 1) + (w & 1)) * 1024 + (h >> 1) * 32 + (w >> 1)] = la - lb;
  }
  __syncthreads();

  // ---- conv1 + lrelu + squeeze -> bufB (48,16,16) ----
  ldsum += conv1_plane(bufA, bufB, k1, __ldg(b1 + wid), wid, lane);
  if (wid < 4)
    ldsum += conv1_plane(bufA, bufB, k1, __ldg(b1 + 8 + wid), 8 + wid, lane);
  __syncthreads();

  // ---- conv2 + lrelu + squeeze -> bufA (192,8,8) ----
  ldsum += conv2_triple(bufB, bufA, k2, b2, wid * 6,     lane);
  ldsum += conv2_triple(bufB, bufA, k2, b2, wid * 6 + 3, lane);

  // ---- conv3 -> out; thread = (og of 6 outs, h); weights staged via SMEM ----
  {
    int og = tid >> 3;               // 0..31
    int h  = tid & 7;
    int hm = (h + 7) & 7, hp = (h + 1) & 7;
    float acc[6][8];
#pragma unroll
    for (int oo = 0; oo < 6; oo++)
#pragma unroll
      for (int ww = 0; ww < 8; ww++) acc[oo][ww] = 0.f;

#pragma unroll 1
    for (int cc = 0; cc < 192; cc += CH) {
      // stage CH input channels' worth of weights into bufB (coalesced)
      __syncthreads();   // conv2 done reading bufB (first iter) / compute done (rest)
      {
        const float4* src = (const float4*)(g_w3p + cc * 1728);
        float4* dst = (float4*)bufB;
#pragma unroll
        for (int t = 0; t < (CH * 1728) / (4 * 256); t++)
          dst[tid + t * 256] = src[tid + t * 256];
        // remainder (CH*1728/4 = 2592 = 10*256 + 32)
        int rem = tid + ((CH * 1728) / (4 * 256)) * 256;
        if (rem < CH * 1728 / 4) dst[rem] = src[rem];
      }
      __syncthreads();

#pragma unroll 1
      for (int ii = 0; ii < CH; ii++) {
        const float* rb = bufA + (cc + ii) * 64;
        float rm[8], r0[8], rp[8];
        {
          float4 t0 = *(const float4*)(rb + hm * 8);
          float4 t1 = *(const float4*)(rb + hm * 8 + 4);
          rm[0]=t0.x; rm[1]=t0.y; rm[2]=t0.z; rm[3]=t0.w; rm[4]=t1.x; rm[5]=t1.y; rm[6]=t1.z; rm[7]=t1.w;
          t0 = *(const float4*)(rb + h * 8);
          t1 = *(const float4*)(rb + h * 8 + 4);
          r0[0]=t0.x; r0[1]=t0.y; r0[2]=t0.z; r0[3]=t0.w; r0[4]=t1.x; r0[5]=t1.y; r0[6]=t1.z; r0[7]=t1.w;
          t0 = *(const float4*)(rb + hp * 8);
          t1 = *(const float4*)(rb + hp * 8 + 4);
          rp[0]=t0.x; rp[1]=t0.y; rp[2]=t0.z; rp[3]=t0.w; rp[4]=t1.x; rp[5]=t1.y; rp[6]=t1.z; rp[7]=t1.w;
        }
        const float* wbi = bufB + ii * 1728 + og * 6;
#pragma unroll
        for (int dy = 0; dy < 3; dy++) {
#pragma unroll
          for (int dx = 0; dx < 3; dx++) {
            // 3 x LDS.64, broadcast within 8-lane h-groups, 4 og-banks apart
            const float2* wp = (const float2*)(wbi + (dy * 3 + dx) * 192);
            float2 wa = wp[0], wb2 = wp[1], wc = wp[2];
            float ws[6] = {wa.x, wa.y, wb2.x, wb2.y, wc.x, wc.y};
#pragma unroll
            for (int oo = 0; oo < 6; oo++) {
              float wv = ws[oo];
              if (dy == 0) {
#pragma unroll
                for (int ww = 0; ww < 8; ww++)
                  acc[oo][ww] = fmaf(wv, rm[(ww + dx + 7) & 7], acc[oo][ww]);
              } else if (dy == 1) {
#pragma unroll
                for (int ww = 0; ww < 8; ww++)
                  acc[oo][ww] = fmaf(wv, r0[(ww + dx + 7) & 7], acc[oo][ww]);
              } else {
#pragma unroll
                for (int ww = 0; ww < 8; ww++)
                  acc[oo][ww] = fmaf(wv, rp[(ww + dx + 7) & 7], acc[oo][ww]);
              }
            }
          }
        }
      }
    }

    float* yo = out + (size_t)b * 12288 + h * 8;
#pragma unroll
    for (int oo = 0; oo < 6; oo++) {
      int o = og * 6 + oo;
      float bias = __ldg(b3 + o);
      float y0 = acc[oo][0] + bias, y1 = acc[oo][1] + bias;
      float y2 = acc[oo][2] + bias, y3 = acc[oo][3] + bias;
      float y4 = acc[oo][4] + bias, y5 = acc[oo][5] + bias;
      float y6 = acc[oo][6] + bias, y7 = acc[oo][7] + bias;
      ldsum -= 0.5f * (y0*y0 + y1*y1 + y2*y2 + y3*y3 + y4*y4 + y5*y5 + y6*y6 + y7*y7);
      *(float4*)(yo + o * 64)     = make_float4(y0, y1, y2, y3);
      *(float4*)(yo + o * 64 + 4) = make_float4(y4, y5, y6, y7);
    }
  }

  // ---- per-sample log_pdf reduction ----
#pragma unroll
  for (int off = 16; off > 0; off >>= 1) ldsum += __shfl_down_sync(FULLMASK, ldsum, off);
  if (lane == 0) red[wid] = ldsum;
  __syncthreads();
  if (tid == 0) {
    float t = 0.f;
#pragma unroll
    for (int i = 0; i < 8; i++) t += red[i];
    out[512 * 12288 + b] = t - 0.5f * 1.8378770664093453f * 12288.0f + g_convld;
  }
}

// ============================================================================
extern "C" void kernel_launch(void* const* d_in, const int* in_sizes, int n_in,
                              void* d_out, int out_size) {
  // map inputs by element count (all sizes distinct) — robust to ordering
  const float *x = 0, *k1 = 0, *b1 = 0, *k2 = 0, *b2 = 0, *k3 = 0, *b3 = 0;
  for (int i = 0; i < n_in; i++) {
    const float* p = (const float*)d_in[i];
    switch (in_sizes[i]) {
      case 512 * 12288:   x  = p; break;
      case 12 * 12 * 9:   k1 = p; break;
      case 12:            b1 = p; break;
      case 48 * 48 * 9:   k2 = p; break;
      case 48:            b2 = p; break;
      case 192 * 192 * 9: k3 = p; break;
      case 192:           b3 = p; break;
    }
  }
  float* out = (float*)d_out;

  const int SMEM_BYTES = 2 * 12288 * 4;   // 98304
  cudaFuncSetAttribute(k_main, cudaFuncAttributeMaxDynamicSharedMemorySize, SMEM_BYTES);

  k_pack<<<(192 * 192 * 9 + 255) / 256, 256>>>(k3);   // also zeroes g_convld
  k_logdet<<<160, 256>>>(k1, k2, k3);
  k_main<<<512, 256, SMEM_BYTES>>>(x, k1, b1, k2, b2, b3, out);
}